// round 13
// baseline (speedup 1.0000x reference)
#include <cuda_runtime.h>
#include <cstdint>

// fields: (B=64, H=512, W=512, C=6) float32
// pump_indices: (B, 2) int32
// out: (B, H, W, 4) float32 — per-sample mean of the 5x5 window over channels
//                             [2:6], broadcast over the whole (H, W) plane.
//
// Fused, barrier-free kernel at the measured-optimal geometry
// (16384 blocks x 128 thr, 16 KB of stores per block). The per-warp
// 25-pixel window-mean reduction uses packed add.rn.f32x2 (sm_103a) so the
// butterfly tree costs 10 packed adds instead of 20 scalar FADDs, shrinking
// the replicated prologue across 65536 warps.

#define H_DIM 512
#define W_DIM 512
#define C_DIM 6
#define RADIUS 2
#define WIN 5              // 2*RADIUS+1
#define WIN_PIX (WIN*WIN)  // 25
#define HW (H_DIM * W_DIM) // 262144 pixels per sample

#define FILL_THREADS 128
#define FILL_ITERS 8       // 128 thr * 8 * 16 B = 16 KB per block
// grid.x = HW / (FILL_THREADS * FILL_ITERS) = 256

__device__ __forceinline__ uint64_t pack_f2(float lo, float hi) {
    uint64_t r;
    asm("mov.b64 %0, {%1, %2};" : "=l"(r) : "f"(lo), "f"(hi));
    return r;
}

__device__ __forceinline__ void unpack_f2(uint64_t v, float& lo, float& hi) {
    asm("mov.b64 {%0, %1}, %2;" : "=f"(lo), "=f"(hi) : "l"(v));
}

__device__ __forceinline__ uint64_t add_f32x2(uint64_t a, uint64_t b) {
    uint64_t r;
    asm("add.rn.f32x2 %0, %1, %2;" : "=l"(r) : "l"(a), "l"(b));
    return r;
}

__global__ void __launch_bounds__(FILL_THREADS)
fused_f32x2_kernel(const float* __restrict__ fields,
                   const int* __restrict__ pump_indices,
                   float4* __restrict__ out) {
    const int b = blockIdx.y;
    const int lane = threadIdx.x & 31;

    // ---- every warp: redundant window-mean computation (no barriers) ----
    const int2 pidx = __ldg(reinterpret_cast<const int2*>(pump_indices) + b);
    const int py = pidx.x;
    const int px = pidx.y;

    uint64_t v01 = 0, v23 = 0;  // packed {c2,c3}, {c4,c5} accumulators
    if (lane < WIN_PIX) {
        const int dy = lane / WIN;
        const int dx = lane % WIN;
        const int y = py - RADIUS + dy;
        const int x = px - RADIUS + dx;
        // channel offset 2 within a 6-float pixel -> 8-byte aligned
        const float* p = fields
            + ((size_t)b * HW + (size_t)y * W_DIM + x) * C_DIM + 2;
        float2 a = __ldg(reinterpret_cast<const float2*>(p));
        float2 c = __ldg(reinterpret_cast<const float2*>(p + 2));
        v01 = pack_f2(a.x, a.y);
        v23 = pack_f2(c.x, c.y);
    }

    // Butterfly reduce on packed f32x2: 5 steps x 2 packed adds.
    #pragma unroll
    for (int off = 16; off > 0; off >>= 1) {
        v01 = add_f32x2(v01, __shfl_xor_sync(0xFFFFFFFFu, v01, off));
        v23 = add_f32x2(v23, __shfl_xor_sync(0xFFFFFFFFu, v23, off));
    }

    float s0, s1, s2, s3;
    unpack_f2(v01, s0, s1);
    unpack_f2(v23, s2, s3);

    const float inv = 1.0f / (float)WIN_PIX;
    const float4 m = make_float4(s0 * inv, s1 * inv, s2 * inv, s3 * inv);

    // ---- coalesced float4 store stream: 16 KB per block ----
    float4* dst = out + (size_t)b * HW
                      + (size_t)blockIdx.x * (FILL_THREADS * FILL_ITERS)
                      + threadIdx.x;
    #pragma unroll
    for (int i = 0; i < FILL_ITERS; ++i) {
        dst[i * FILL_THREADS] = m;
    }
}

extern "C" void kernel_launch(void* const* d_in, const int* in_sizes, int n_in,
                              void* d_out, int out_size) {
    const float* fields = (const float*)d_in[0];
    const int* pump_indices = (const int*)d_in[1];
    float4* out = (float4*)d_out;

    const int B = in_sizes[1] / 2;  // (B, 2) int32

    dim3 grid(HW / (FILL_THREADS * FILL_ITERS), B);
    fused_f32x2_kernel<<<grid, FILL_THREADS>>>(fields, pump_indices, out);
}

// round 14
// speedup vs baseline: 1.0124x; 1.0124x over previous
#include <cuda_runtime.h>

// fields: (B=64, H=512, W=512, C=6) float32
// pump_indices: (B, 2) int32
// out: (B, H, W, 4) float32 — per-sample mean of the 5x5 window over channels
//                             [2:6], broadcast over the whole (H, W) plane.
//
// FINAL (R9 geometry — measured optimum over an 11-point search):
//   grid = (256, 64) = 16384 blocks x 128 thr, 16 KB of float4 stores/block.
//   Barrier-free: every warp redundantly computes its sample's 25-pixel
//   window mean (2 predicated float2 loads + butterfly shuffle reduce;
//   no smem, no __syncthreads), then streams coalesced float4 stores.
//   Kernel time 39.6 us = 2.3% over the pure-fill store floor (38.66 us,
//   itself at the B300 LTS ~6300 B/cyc path-independent cap).
//   Coarser and finer geometries, .cs stores, redux.sync, and packed f32x2
//   reductions all measured worse.

#define H_DIM 512
#define W_DIM 512
#define C_DIM 6
#define RADIUS 2
#define WIN 5              // 2*RADIUS+1
#define WIN_PIX (WIN*WIN)  // 25
#define HW (H_DIM * W_DIM) // 262144 pixels per sample

#define FILL_THREADS 128
#define FILL_ITERS 8       // 128 thr * 8 * 16 B = 16 KB per block
// grid.x = HW / (FILL_THREADS * FILL_ITERS) = 256

__global__ void __launch_bounds__(FILL_THREADS)
fused_128t_kernel(const float* __restrict__ fields,
                  const int* __restrict__ pump_indices,
                  float4* __restrict__ out) {
    const int b = blockIdx.y;
    const int lane = threadIdx.x & 31;

    // ---- every warp: redundant window-mean computation (no barriers) ----
    // Single 64-bit load for (py, px).
    const int2 pidx = __ldg(reinterpret_cast<const int2*>(pump_indices) + b);
    const int py = pidx.x;
    const int px = pidx.y;

    float s0 = 0.f, s1 = 0.f, s2 = 0.f, s3 = 0.f;
    if (lane < WIN_PIX) {
        const int dy = lane / WIN;
        const int dx = lane % WIN;
        const int y = py - RADIUS + dy;
        const int x = px - RADIUS + dx;
        // channel offset 2 within a 6-float pixel -> 8-byte aligned
        const float* p = fields
            + ((size_t)b * HW + (size_t)y * W_DIM + x) * C_DIM + 2;
        float2 a = __ldg(reinterpret_cast<const float2*>(p));
        float2 c = __ldg(reinterpret_cast<const float2*>(p + 2));
        s0 = a.x; s1 = a.y; s2 = c.x; s3 = c.y;
    }

    // Butterfly reduce: all 32 lanes end with the full sum.
    #pragma unroll
    for (int off = 16; off > 0; off >>= 1) {
        s0 += __shfl_xor_sync(0xFFFFFFFFu, s0, off);
        s1 += __shfl_xor_sync(0xFFFFFFFFu, s1, off);
        s2 += __shfl_xor_sync(0xFFFFFFFFu, s2, off);
        s3 += __shfl_xor_sync(0xFFFFFFFFu, s3, off);
    }

    const float inv = 1.0f / (float)WIN_PIX;
    const float4 m = make_float4(s0 * inv, s1 * inv, s2 * inv, s3 * inv);

    // ---- coalesced float4 store stream: 16 KB per block ----
    float4* dst = out + (size_t)b * HW
                      + (size_t)blockIdx.x * (FILL_THREADS * FILL_ITERS)
                      + threadIdx.x;
    #pragma unroll
    for (int i = 0; i < FILL_ITERS; ++i) {
        dst[i * FILL_THREADS] = m;
    }
}

extern "C" void kernel_launch(void* const* d_in, const int* in_sizes, int n_in,
                              void* d_out, int out_size) {
    const float* fields = (const float*)d_in[0];
    const int* pump_indices = (const int*)d_in[1];
    float4* out = (float4*)d_out;

    const int B = in_sizes[1] / 2;  // (B, 2) int32

    dim3 grid(HW / (FILL_THREADS * FILL_ITERS), B);
    fused_128t_kernel<<<grid, FILL_THREADS>>>(fields, pump_indices, out);
}